// round 1
// baseline (speedup 1.0000x reference)
#include <cuda_runtime.h>

// SNSCell: B=64 batch, S=512 sensory, N=512 state, M=128 motor, 6 unfolds, dt=0.1
#define Bn 64
#define Nn 512
#define Sn 512
#define Mn 128
#define NUNF 6
#define DELTA (0.1f / 6.0f)

#define JT 32          // j (postsynaptic) tile per CTA
#define NJT 16         // Nn / JT
#define KS 16          // i-reduction splits
#define CI 32          // i (presynaptic) chunk per CTA  (512/KS)
#define TPB 256
#define VS_STRIDE 68   // padded smem row stride (floats), 16B aligned, conflict-light

// ---------------- scratch (static device memory; no allocations) ----------------
__device__ float4 g_P[Nn * Nn];    // fused internal params {1/2s, (s-mu)/2s, mask*erev, mask*w}
__device__ float4 g_SP[Sn * Nn];   // fused sensory params
__device__ float  g_x[Bn * Sn];    // mapped inputs
__device__ float  g_v[2 * Bn * Nn];// ping-pong state
__device__ float  g_srev[Bn * Nn]; // sensory rev sum + bias
__device__ float  g_sw[Bn * Nn];   // sensory w sum
__device__ float  g_accR[Bn * Nn]; // split-i accumulators (kept zeroed between uses)
__device__ float  g_accW[Bn * Nn];
__device__ unsigned g_cnt[NJT];    // per-j-tile arrival counters (kept zeroed)

__device__ __forceinline__ float satfma(float a, float b, float c) {
    float d;
    asm("fma.rn.sat.f32 %0, %1, %2, %3;" : "=f"(d) : "f"(a), "f"(b), "f"(c));
    return d;
}

// ---------------- prep: fuse parameters, map inputs, zero accumulators ----------------
__global__ void prep_kernel(const float* __restrict__ sigma, const float* __restrict__ mu,
                            const float* __restrict__ erev,  const float* __restrict__ wmat,
                            const float* __restrict__ mask,
                            const float* __restrict__ ssigma, const float* __restrict__ smu,
                            const float* __restrict__ serev,  const float* __restrict__ swmat,
                            const float* __restrict__ smask,
                            const float* __restrict__ inputs, const float* __restrict__ iw,
                            const float* __restrict__ ib)
{
    int stride = gridDim.x * blockDim.x;
    int tid = blockIdx.x * blockDim.x + threadIdx.x;
    for (int i = tid; i < Nn * Nn; i += stride) {
        float sg = sigma[i];
        float a  = 1.0f / (2.0f * sg);
        float4 p;
        p.x = a;
        p.y = (sg - mu[i]) * a;
        float mk = mask[i];
        p.z = mk * erev[i];
        p.w = mk * wmat[i];
        g_P[i] = p;
    }
    for (int i = tid; i < Sn * Nn; i += stride) {
        float sg = ssigma[i];
        float a  = 1.0f / (2.0f * sg);
        float4 p;
        p.x = a;
        p.y = (sg - smu[i]) * a;
        float mk = smask[i];
        p.z = mk * serev[i];
        p.w = mk * swmat[i];
        g_SP[i] = p;
    }
    for (int i = tid; i < Bn * Sn; i += stride) {
        int s = i & (Sn - 1);
        g_x[i] = fmaf(inputs[i], iw[s], ib[s]);
    }
    for (int i = tid; i < Bn * Nn; i += stride) {
        g_accR[i] = 0.0f;
        g_accW[i] = 0.0f;
    }
    if (tid < NJT) g_cnt[tid] = 0u;
}

// ---------------- core reduction body (shared by sensory + step kernels) ----------------
// CTA = (j-tile jt of 32 postsyn, i-chunk kc of 32 presyn), covers all 64 batches.
// Warp w handles batches [8w, 8w+8) for all 32 j of the tile (lane = j).
__device__ __forceinline__ void reduce_body(const float4* __restrict__ P,
                                            const float*  __restrict__ xin,
                                            int jt, int kc, float* vs)
{
    int tid = threadIdx.x;
    int i0  = kc * CI;
    // stage x/v chunk transposed: vs[il][b], coalesced global reads
    for (int t = tid; t < CI * Bn; t += TPB) {
        int il = t & (CI - 1);
        int b  = t >> 5;
        vs[il * VS_STRIDE + b] = xin[b * 512 + i0 + il];
    }
    __syncthreads();

    int lane = tid & 31;
    int warp = tid >> 5;
    int jg = jt * JT + lane;
    int b0 = warp * 8;

    float r[8], wv[8];
#pragma unroll
    for (int k = 0; k < 8; k++) { r[k] = 0.0f; wv[k] = 0.0f; }

    const float4* Pp = P + (size_t)i0 * Nn + jg;
#pragma unroll 4
    for (int il = 0; il < CI; il++) {
        float4 p = __ldg(Pp + (size_t)il * Nn);
        const float4* v4 = reinterpret_cast<const float4*>(vs + il * VS_STRIDE + b0);
        float4 va = v4[0];
        float4 vb = v4[1];
        float g;
        g = satfma(va.x, p.x, p.y); r[0] = fmaf(g, p.z, r[0]); wv[0] = fmaf(g, p.w, wv[0]);
        g = satfma(va.y, p.x, p.y); r[1] = fmaf(g, p.z, r[1]); wv[1] = fmaf(g, p.w, wv[1]);
        g = satfma(va.z, p.x, p.y); r[2] = fmaf(g, p.z, r[2]); wv[2] = fmaf(g, p.w, wv[2]);
        g = satfma(va.w, p.x, p.y); r[3] = fmaf(g, p.z, r[3]); wv[3] = fmaf(g, p.w, wv[3]);
        g = satfma(vb.x, p.x, p.y); r[4] = fmaf(g, p.z, r[4]); wv[4] = fmaf(g, p.w, wv[4]);
        g = satfma(vb.y, p.x, p.y); r[5] = fmaf(g, p.z, r[5]); wv[5] = fmaf(g, p.w, wv[5]);
        g = satfma(vb.z, p.x, p.y); r[6] = fmaf(g, p.z, r[6]); wv[6] = fmaf(g, p.w, wv[6]);
        g = satfma(vb.w, p.x, p.y); r[7] = fmaf(g, p.z, r[7]); wv[7] = fmaf(g, p.w, wv[7]);
    }

#pragma unroll
    for (int k = 0; k < 8; k++) {
        int idx = (b0 + k) * Nn + jg;   // lanes -> consecutive jg: coalesced REDG
        atomicAdd(&g_accR[idx], r[k]);
        atomicAdd(&g_accW[idx], wv[k]);
    }
}

// ---------------- sensory pass: fills g_srev (+bias) / g_sw, re-zeros accumulators ----------------
__global__ void __launch_bounds__(TPB, 2) sensory_kernel(const float* __restrict__ bias)
{
    __shared__ __align__(16) float vs[CI * VS_STRIDE];
    int jt = blockIdx.x, kc = blockIdx.y;
    reduce_body(g_SP, g_x, jt, kc, vs);

    __threadfence();
    __syncthreads();
    __shared__ int lastFlag;
    if (threadIdx.x == 0)
        lastFlag = (atomicAdd(&g_cnt[jt], 1u) == (unsigned)(gridDim.y - 1));
    __syncthreads();
    if (lastFlag) {
        int lane = threadIdx.x & 31, warp = threadIdx.x >> 5;
        int jg = jt * JT + lane;
        int b0 = warp * 8;
        float bj = bias[jg];
#pragma unroll
        for (int k = 0; k < 8; k++) {
            int idx = (b0 + k) * Nn + jg;
            float ar = g_accR[idx];
            float aw = g_accW[idx];
            g_srev[idx] = ar + bj;
            g_sw[idx]   = aw;
            g_accR[idx] = 0.0f;
            g_accW[idx] = 0.0f;
        }
        if (threadIdx.x == 0) g_cnt[jt] = 0u;
    }
}

// ---------------- one unfold step (fused reduce + v-update via last-block) ----------------
// vn = (tau*v + delta*sum_rev) / (tau + delta + delta*sum_w)   [algebraically == reference]
template <bool LAST>
__global__ void __launch_bounds__(TPB, 2) step_kernel(const float* __restrict__ vin,
                                                      float* __restrict__ vout,
                                                      const float* __restrict__ tau,
                                                      float* __restrict__ outp,
                                                      const float* __restrict__ ow,
                                                      const float* __restrict__ ob)
{
    __shared__ __align__(16) float vs[CI * VS_STRIDE];
    int jt = blockIdx.x, kc = blockIdx.y;
    reduce_body(g_P, vin, jt, kc, vs);

    __threadfence();
    __syncthreads();
    __shared__ int lastFlag;
    if (threadIdx.x == 0)
        lastFlag = (atomicAdd(&g_cnt[jt], 1u) == (unsigned)(gridDim.y - 1));
    __syncthreads();
    if (lastFlag) {
        int lane = threadIdx.x & 31, warp = threadIdx.x >> 5;
        int jg = jt * JT + lane;
        int b0 = warp * 8;
        float tj = tau[jg];
        int mo = jg - (Nn - Mn);
        float owj = 0.0f, obj = 0.0f;
        if (LAST && mo >= 0 && ow != nullptr) { owj = ow[mo]; obj = ob[mo]; }
#pragma unroll
        for (int k = 0; k < 8; k++) {
            int idx = (b0 + k) * Nn + jg;
            float sr = g_accR[idx] + g_srev[idx];
            float sw = g_accW[idx] + g_sw[idx];
            float v  = vin[idx];
            float vn = (tj * v + DELTA * sr) / (tj + DELTA + DELTA * sw);
            vout[idx] = vn;
            g_accR[idx] = 0.0f;
            g_accW[idx] = 0.0f;
            if (LAST && outp != nullptr && mo >= 0)
                outp[(b0 + k) * Mn + mo] = fmaf(vn, owj, obj);
        }
        if (threadIdx.x == 0) g_cnt[jt] = 0u;
    }
}

// ---------------- host ----------------
extern "C" void kernel_launch(void* const* d_in, const int* in_sizes, int n_in,
                              void* d_out, int out_size)
{
    const float* inputs = (const float*)d_in[0];
    const float* states = (const float*)d_in[1];
    const float* tau    = (const float*)d_in[2];
    const float* bias   = (const float*)d_in[3];
    const float* erev   = (const float*)d_in[4];
    const float* wmat   = (const float*)d_in[5];
    const float* sigma  = (const float*)d_in[6];
    const float* mu     = (const float*)d_in[7];
    const float* serev  = (const float*)d_in[8];
    const float* swmat  = (const float*)d_in[9];
    const float* ssigma = (const float*)d_in[10];
    const float* smu    = (const float*)d_in[11];
    const float* mask   = (const float*)d_in[12];
    const float* smask  = (const float*)d_in[13];
    const float* iw     = (const float*)d_in[14];
    const float* ib     = (const float*)d_in[15];
    const float* ow     = (const float*)d_in[16];
    const float* ob     = (const float*)d_in[17];
    float* outF = (float*)d_out;

    float* vbuf = nullptr;
    cudaGetSymbolAddress((void**)&vbuf, g_v);

    prep_kernel<<<512, TPB>>>(sigma, mu, erev, wmat, mask,
                              ssigma, smu, serev, swmat, smask,
                              inputs, iw, ib);

    dim3 red(NJT, KS);
    sensory_kernel<<<red, TPB>>>(bias);

    const float* cur = states;
    for (int u = 0; u < NUNF; u++) {
        bool last = (u == NUNF - 1);
        float* nxt = vbuf + (u & 1) * (Bn * Nn);
        float* outp = nullptr;
        if (last) {
            // output is tuple (out[B,M], v[B,N]) flattened in order
            if (out_size >= Bn * Mn + Bn * Nn) { nxt = outF + Bn * Mn; outp = outF; }
            else if (out_size == Bn * Nn)      { nxt = outF; }
            else if (out_size >= Bn * Mn)      { outp = outF; }
        }
        if (last) step_kernel<true><<<red, TPB>>>(cur, nxt, tau, outp, ow, ob);
        else      step_kernel<false><<<red, TPB>>>(cur, nxt, tau, nullptr, ow, ob);
        cur = nxt;
    }
}

// round 3
// speedup vs baseline: 1.2017x; 1.2017x over previous
#include <cuda_runtime.h>

// SNSCell: B=64 batch, S=512 sensory, N=512 state, M=128 motor, 6 unfolds, dt=0.1
#define Bn 64
#define Nn 512
#define Sn 512
#define Mn 128
#define NUNF 6
#define DELTA (0.1f / 6.0f)

#define JT 32          // j (postsynaptic) tile per CTA (lane = j)
#define NJT 16         // Nn / JT
#define KS 16          // i-reduction splits
#define CI 32          // i (presynaptic) chunk per CTA
#define TPB 512        // 16 warps; warp -> 4 batches
#define VST 68         // padded smem stride for v chunk (floats), %4==0 for LDS.128

// ---------------- scratch (static device memory; no allocations) ----------------
__device__ float4 g_P[Nn * Nn];    // fused internal params {1/2s, (s-mu)/2s, mask*erev, mask*w}
__device__ float4 g_SP[Sn * Nn];   // fused sensory params
__device__ float  g_x[Bn * Sn];    // mapped inputs
__device__ float  g_v[2 * Bn * Nn];// ping-pong state
__device__ float  g_srev[Bn * Nn]; // sensory rev sum + bias
__device__ float  g_sw[Bn * Nn];   // sensory w sum
__device__ float  g_accR[Bn * Nn]; // split-i accumulators (kept zeroed between uses)
__device__ float  g_accW[Bn * Nn];
__device__ unsigned g_cnt[NJT];    // per-j-tile arrival counters (kept zeroed)

__device__ __forceinline__ float satfma(float a, float b, float c) {
    float d;
    asm("fma.rn.sat.f32 %0, %1, %2, %3;" : "=f"(d) : "f"(a), "f"(b), "f"(c));
    return d;
}

// ---------------- prep: fuse parameters (vectorized), map inputs, zero accumulators ----------------
__device__ __forceinline__ float4 fuse1(float sg, float m, float e, float wv, float mk) {
    float a = 1.0f / (2.0f * sg);
    float4 p;
    p.x = a;
    p.y = (sg - m) * a;
    p.z = mk * e;
    p.w = mk * wv;
    return p;
}

__global__ void prep_kernel(const float* __restrict__ sigma, const float* __restrict__ mu,
                            const float* __restrict__ erev,  const float* __restrict__ wmat,
                            const float* __restrict__ mask,
                            const float* __restrict__ ssigma, const float* __restrict__ smu,
                            const float* __restrict__ serev,  const float* __restrict__ swmat,
                            const float* __restrict__ smask,
                            const float* __restrict__ inputs, const float* __restrict__ iw,
                            const float* __restrict__ ib)
{
    int stride = gridDim.x * blockDim.x;
    int tid = blockIdx.x * blockDim.x + threadIdx.x;

    const float4* sg4 = (const float4*)sigma;
    const float4* mu4 = (const float4*)mu;
    const float4* er4 = (const float4*)erev;
    const float4* w4  = (const float4*)wmat;
    const float4* mk4 = (const float4*)mask;
    for (int i = tid; i < Nn * Nn / 4; i += stride) {
        float4 sg = sg4[i], m = mu4[i], e = er4[i], ww = w4[i], mk = mk4[i];
        g_P[4*i+0] = fuse1(sg.x, m.x, e.x, ww.x, mk.x);
        g_P[4*i+1] = fuse1(sg.y, m.y, e.y, ww.y, mk.y);
        g_P[4*i+2] = fuse1(sg.z, m.z, e.z, ww.z, mk.z);
        g_P[4*i+3] = fuse1(sg.w, m.w, e.w, ww.w, mk.w);
    }
    const float4* ssg4 = (const float4*)ssigma;
    const float4* smu4 = (const float4*)smu;
    const float4* ser4 = (const float4*)serev;
    const float4* sw4  = (const float4*)swmat;
    const float4* smk4 = (const float4*)smask;
    for (int i = tid; i < Sn * Nn / 4; i += stride) {
        float4 sg = ssg4[i], m = smu4[i], e = ser4[i], ww = sw4[i], mk = smk4[i];
        g_SP[4*i+0] = fuse1(sg.x, m.x, e.x, ww.x, mk.x);
        g_SP[4*i+1] = fuse1(sg.y, m.y, e.y, ww.y, mk.y);
        g_SP[4*i+2] = fuse1(sg.z, m.z, e.z, ww.z, mk.z);
        g_SP[4*i+3] = fuse1(sg.w, m.w, e.w, ww.w, mk.w);
    }
    const float4* in4 = (const float4*)inputs;
    const float4* iw4 = (const float4*)iw;
    const float4* ib4 = (const float4*)ib;
    float4* x4 = (float4*)g_x;
    for (int i = tid; i < Bn * Sn / 4; i += stride) {
        int s4i = i & (Sn / 4 - 1);
        float4 a = in4[i], wv = iw4[s4i], bv = ib4[s4i];
        float4 o;
        o.x = fmaf(a.x, wv.x, bv.x);
        o.y = fmaf(a.y, wv.y, bv.y);
        o.z = fmaf(a.z, wv.z, bv.z);
        o.w = fmaf(a.w, wv.w, bv.w);
        x4[i] = o;
    }
    float4 z = make_float4(0.f, 0.f, 0.f, 0.f);
    float4* aR = (float4*)g_accR;
    float4* aW = (float4*)g_accW;
    for (int i = tid; i < Bn * Nn / 4; i += stride) { aR[i] = z; aW[i] = z; }
    if (tid < NJT) g_cnt[tid] = 0u;
}

// ---------------- core reduction body (shared by sensory + step kernels) ----------------
// CTA = (j-tile jt of 32 postsyn, i-chunk kc of 32 presyn). 16 warps; warp w -> batches [4w,4w+4);
// lane = j. Operands fully staged in shared memory, main loop is LDS + FFMA only.
__device__ __forceinline__ void reduce_body(const float4* __restrict__ P,
                                            const float*  __restrict__ xin,
                                            int jt, int kc,
                                            float* vs, float4* ps,
                                            float* r, float* wv)
{
    int tid = threadIdx.x;
    int i0  = kc * CI;
    int jc0 = jt * JT;

    // stage v/x chunk transposed: vs[il][b] (128B-contiguous global reads per 32 lanes)
    for (int t = tid; t < CI * Bn; t += TPB) {
        int il = t & (CI - 1);
        int b  = t >> 5;
        vs[il * VST + b] = xin[b * 512 + i0 + il];
    }
    // stage P tile: ps[il*32 + jl]  (512B-contiguous global reads per 32 lanes)
    for (int t = tid; t < CI * JT; t += TPB) {
        int row = t >> 5;
        int col = t & 31;
        ps[t] = __ldg(&P[(size_t)(i0 + row) * Nn + jc0 + col]);
    }
    __syncthreads();

    int lane = tid & 31;
    int warp = tid >> 5;
    int b0 = warp * 4;

#pragma unroll
    for (int k = 0; k < 4; k++) { r[k] = 0.0f; wv[k] = 0.0f; }

#pragma unroll 8
    for (int il = 0; il < CI; il++) {
        float4 p = ps[il * JT + lane];                                     // conflict-free LDS.128
        float4 v = *reinterpret_cast<const float4*>(vs + il * VST + b0);   // broadcast LDS.128
        float g;
        g = satfma(v.x, p.x, p.y); r[0] = fmaf(g, p.z, r[0]); wv[0] = fmaf(g, p.w, wv[0]);
        g = satfma(v.y, p.x, p.y); r[1] = fmaf(g, p.z, r[1]); wv[1] = fmaf(g, p.w, wv[1]);
        g = satfma(v.z, p.x, p.y); r[2] = fmaf(g, p.z, r[2]); wv[2] = fmaf(g, p.w, wv[2]);
        g = satfma(v.w, p.x, p.y); r[3] = fmaf(g, p.z, r[3]); wv[3] = fmaf(g, p.w, wv[3]);
    }
}

__device__ __forceinline__ void accum_atomics(const float* r, const float* wv, int jg, int b0)
{
#pragma unroll
    for (int k = 0; k < 4; k++) {
        int idx = (b0 + k) * Nn + jg;   // lanes -> consecutive jg: coalesced REDG
        atomicAdd(&g_accR[idx], r[k]);
        atomicAdd(&g_accW[idx], wv[k]);
    }
}

// ---------------- sensory pass: fills g_srev (+bias) / g_sw, re-zeros accumulators ----------------
__global__ void __launch_bounds__(TPB, 2) sensory_kernel(const float* __restrict__ bias)
{
    __shared__ __align__(16) float vs[CI * VST];
    __shared__ __align__(16) float4 ps[CI * JT];
    int jt = blockIdx.x, kc = blockIdx.y;
    float r[4], wv[4];
    reduce_body(g_SP, g_x, jt, kc, vs, ps, r, wv);

    int lane = threadIdx.x & 31, warp = threadIdx.x >> 5;
    int jg = jt * JT + lane;
    int b0 = warp * 4;
    accum_atomics(r, wv, jg, b0);

    __threadfence();
    __syncthreads();
    __shared__ int lastFlag;
    if (threadIdx.x == 0)
        lastFlag = (atomicAdd(&g_cnt[jt], 1u) == (unsigned)(gridDim.y - 1));
    __syncthreads();
    if (lastFlag) {
        float bj = bias[jg];
#pragma unroll
        for (int k = 0; k < 4; k++) {
            int idx = (b0 + k) * Nn + jg;
            g_srev[idx] = g_accR[idx] + bj;
            g_sw[idx]   = g_accW[idx];
            g_accR[idx] = 0.0f;
            g_accW[idx] = 0.0f;
        }
        if (threadIdx.x == 0) g_cnt[jt] = 0u;
    }
}

// ---------------- one unfold step (fused reduce + v-update via last-block) ----------------
// vn = (tau*v + delta*sum_rev) / (tau + delta + delta*sum_w)   [algebraically == reference]
template <bool LAST>
__global__ void __launch_bounds__(TPB, 2) step_kernel(const float* __restrict__ vin,
                                                      float* __restrict__ vout,
                                                      const float* __restrict__ tau,
                                                      float* __restrict__ outp,
                                                      const float* __restrict__ ow,
                                                      const float* __restrict__ ob)
{
    __shared__ __align__(16) float vs[CI * VST];
    __shared__ __align__(16) float4 ps[CI * JT];
    int jt = blockIdx.x, kc = blockIdx.y;
    float r[4], wv[4];
    reduce_body(g_P, vin, jt, kc, vs, ps, r, wv);

    int lane = threadIdx.x & 31, warp = threadIdx.x >> 5;
    int jg = jt * JT + lane;
    int b0 = warp * 4;
    accum_atomics(r, wv, jg, b0);

    __threadfence();
    __syncthreads();
    __shared__ int lastFlag;
    if (threadIdx.x == 0)
        lastFlag = (atomicAdd(&g_cnt[jt], 1u) == (unsigned)(gridDim.y - 1));
    __syncthreads();
    if (lastFlag) {
        float tj = tau[jg];
        int mo = jg - (Nn - Mn);
        float owj = 0.0f, obj = 0.0f;
        if (LAST && mo >= 0 && ow != nullptr) { owj = ow[mo]; obj = ob[mo]; }
#pragma unroll
        for (int k = 0; k < 4; k++) {
            int idx = (b0 + k) * Nn + jg;
            float sr = g_accR[idx] + g_srev[idx];
            float sw = g_accW[idx] + g_sw[idx];
            float v  = vin[idx];
            float vn = (tj * v + DELTA * sr) / (tj + DELTA + DELTA * sw);
            vout[idx] = vn;
            g_accR[idx] = 0.0f;
            g_accW[idx] = 0.0f;
            if (LAST && outp != nullptr && mo >= 0)
                outp[(b0 + k) * Mn + mo] = fmaf(vn, owj, obj);
        }
        if (threadIdx.x == 0) g_cnt[jt] = 0u;
    }
}

// ---------------- host ----------------
extern "C" void kernel_launch(void* const* d_in, const int* in_sizes, int n_in,
                              void* d_out, int out_size)
{
    const float* inputs = (const float*)d_in[0];
    const float* states = (const float*)d_in[1];
    const float* tau    = (const float*)d_in[2];
    const float* bias   = (const float*)d_in[3];
    const float* erev   = (const float*)d_in[4];
    const float* wmat   = (const float*)d_in[5];
    const float* sigma  = (const float*)d_in[6];
    const float* mu     = (const float*)d_in[7];
    const float* serev  = (const float*)d_in[8];
    const float* swmat  = (const float*)d_in[9];
    const float* ssigma = (const float*)d_in[10];
    const float* smu    = (const float*)d_in[11];
    const float* mask   = (const float*)d_in[12];
    const float* smask  = (const float*)d_in[13];
    const float* iw     = (const float*)d_in[14];
    const float* ib     = (const float*)d_in[15];
    const float* ow     = (const float*)d_in[16];
    const float* ob     = (const float*)d_in[17];
    float* outF = (float*)d_out;

    float* vbuf = nullptr;
    cudaGetSymbolAddress((void**)&vbuf, g_v);

    prep_kernel<<<128, TPB>>>(sigma, mu, erev, wmat, mask,
                              ssigma, smu, serev, swmat, smask,
                              inputs, iw, ib);

    dim3 red(NJT, KS);
    sensory_kernel<<<red, TPB>>>(bias);

    const float* cur = states;
    for (int u = 0; u < NUNF; u++) {
        bool last = (u == NUNF - 1);
        float* nxt = vbuf + (u & 1) * (Bn * Nn);
        float* outp = nullptr;
        if (last) {
            // output is tuple (out[B,M], v[B,N]) flattened in order
            if (out_size >= Bn * Mn + Bn * Nn) { nxt = outF + Bn * Mn; outp = outF; }
            else if (out_size == Bn * Nn)      { nxt = outF; }
            else if (out_size >= Bn * Mn)      { outp = outF; }
        }
        if (last) step_kernel<true><<<red, TPB>>>(cur, nxt, tau, outp, ow, ob);
        else      step_kernel<false><<<red, TPB>>>(cur, nxt, tau, nullptr, ow, ob);
        cur = nxt;
    }
}